// round 1
// baseline (speedup 1.0000x reference)
#include <cuda_runtime.h>
#include <cuda_bf16.h>

// ---------------------------------------------------------------------------
// FuseBlock: LN -> 1x1 conv(768) -> dw3x3 -> patch circular-conv attention ->
// LN*v -> 1x1 conv(128)+residual -> LN -> 1x1(256)+bias -> dw3x3 -> gate ->
// 1x1(128)+residual.
// All fp32. Scratch in __device__ globals (no allocation allowed).
// ---------------------------------------------------------------------------

#define HH 256
#define WW 256
#define NPIX 65536          // per-batch pixels
#define BATCH 2

// Scratch buffers (per-batch channel-major [B][C][NPIX])
__device__ float s_hn[128L * 131072];          // 128ch tmp (LN outputs / gate out)
__device__ float s_hidden[768L * 131072];      // 768ch tmp
__device__ float s_qkv[768L * 131072];         // 768ch tmp

// ---------------------------------------------------------------------------
// LayerNorm over channels (biased var, eps inside sqrt), optional elementwise
// multiply by V (for va = v * ln(attn)).
// ---------------------------------------------------------------------------
template <bool HASV>
__global__ void ln_k(const float* __restrict__ X, const float* __restrict__ g,
                     const float* __restrict__ be, const float* __restrict__ V,
                     float* __restrict__ Y, int C,
                     long xbs, long vbs, long ybs)
{
    int b = blockIdx.z;
    const float* x = X + (long)b * xbs;
    const float* v = HASV ? (V + (long)b * vbs) : nullptr;
    float* y = Y + (long)b * ybs;
    int p = blockIdx.x * blockDim.x + threadIdx.x;

    float s = 0.f, s2 = 0.f;
    const float* xp = x + p;
    for (int c = 0; c < C; c++) {
        float t = xp[(long)c * NPIX];
        s += t; s2 += t * t;
    }
    float invC = 1.f / (float)C;
    float m = s * invC;
    float var = s2 * invC - m * m;
    float r = rsqrtf(var + 1e-6f);
    for (int c = 0; c < C; c++) {
        float t = (xp[(long)c * NPIX] - m) * r * g[c] + be[c];
        if (HASV) t *= v[(long)c * NPIX + p];
        y[(long)c * NPIX + p] = t;
    }
}

// ---------------------------------------------------------------------------
// Tiled SGEMM: Y[M, NPIX] = W[M,K] @ X[K, NPIX]  (+bias)  (+residual*scale)
// BM=BN=64, BK=16, TM=TN=4, 256 threads.
// Epilogue RESID: Y[m,n] = R[m,n] + S[m] * (acc + bias)
// ---------------------------------------------------------------------------
template <bool HAS_BIAS, bool RESID>
__global__ void gemm_k(const float* __restrict__ W, const float* __restrict__ X,
                       const float* __restrict__ bias,
                       const float* __restrict__ R, const float* __restrict__ S,
                       float* __restrict__ Y,
                       int M, int K, long xbs, long ybs, long rbs)
{
    constexpr int BM = 64, BN = 64, BK = 16, TM = 4, TN = 4;
    int b = blockIdx.z;
    X += (long)b * xbs;
    Y += (long)b * ybs;
    const float* Rb = RESID ? (R + (long)b * rbs) : nullptr;

    int m0 = blockIdx.y * BM;
    int n0 = blockIdx.x * BN;

    __shared__ float Ws[BK][BM + 4];
    __shared__ float Xs[BK][BN + 4];

    int tid = threadIdx.x;
    float acc[TM][TN];
#pragma unroll
    for (int i = 0; i < TM; i++)
#pragma unroll
        for (int j = 0; j < TN; j++) acc[i][j] = 0.f;

    int wrow = tid >> 2;            // 0..63
    int wcol = (tid & 3) * 4;       // 0,4,8,12
    int xrow = tid >> 4;            // 0..15
    int xcol = (tid & 15) * 4;      // 0..60
    int tm = (tid >> 4) * TM;
    int tn = (tid & 15) * TN;

    for (int k0 = 0; k0 < K; k0 += BK) {
        float4 w4 = *(const float4*)&W[(long)(m0 + wrow) * K + k0 + wcol];
        Ws[wcol + 0][wrow] = w4.x;
        Ws[wcol + 1][wrow] = w4.y;
        Ws[wcol + 2][wrow] = w4.z;
        Ws[wcol + 3][wrow] = w4.w;

        float4 x4 = *(const float4*)&X[(long)(k0 + xrow) * NPIX + n0 + xcol];
        *(float4*)&Xs[xrow][xcol] = x4;

        __syncthreads();
#pragma unroll
        for (int k = 0; k < BK; k++) {
            float wr[TM], xr[TN];
            float4 wv = *(const float4*)&Ws[k][tm];
            wr[0] = wv.x; wr[1] = wv.y; wr[2] = wv.z; wr[3] = wv.w;
            float4 xv = *(const float4*)&Xs[k][tn];
            xr[0] = xv.x; xr[1] = xv.y; xr[2] = xv.z; xr[3] = xv.w;
#pragma unroll
            for (int i = 0; i < TM; i++)
#pragma unroll
                for (int j = 0; j < TN; j++)
                    acc[i][j] += wr[i] * xr[j];
        }
        __syncthreads();
    }

#pragma unroll
    for (int i = 0; i < TM; i++) {
        int m = m0 + tm + i;
        float bi = HAS_BIAS ? bias[m] : 0.f;
        float sc = RESID ? S[m] : 0.f;
#pragma unroll
        for (int j = 0; j < TN; j++) {
            long idx = (long)m * NPIX + n0 + tn + j;
            float v = acc[i][j] + bi;
            if (RESID) v = Rb[idx] + sc * v;
            Y[idx] = v;
        }
    }
}

// ---------------------------------------------------------------------------
// Depthwise 3x3, SAME zero padding. One thread per output pixel.
// blockIdx.y = channel, blockIdx.z = batch.
// ---------------------------------------------------------------------------
__global__ void dwconv3_k(const float* __restrict__ X, const float* __restrict__ Wd,
                          float* __restrict__ Y, long xbs, long ybs)
{
    int b = blockIdx.z;
    int c = blockIdx.y;
    const float* x = X + (long)b * xbs + (long)c * NPIX;
    float* y = Y + (long)b * ybs + (long)c * NPIX;
    const float* w = Wd + c * 9;

    int p = blockIdx.x * blockDim.x + threadIdx.x;
    int yy = p >> 8;
    int xx = p & 255;
    float acc = 0.f;
#pragma unroll
    for (int ky = 0; ky < 3; ky++) {
        int iy = yy + ky - 1;
        if (iy < 0 || iy >= HH) continue;
#pragma unroll
        for (int kx = 0; kx < 3; kx++) {
            int ix = xx + kx - 1;
            if (ix < 0 || ix >= WW) continue;
            acc += w[ky * 3 + kx] * x[iy * WW + ix];
        }
    }
    y[p] = acc;
}

// ---------------------------------------------------------------------------
// Patch FFT attention = per-patch 8x8 circular convolution of q and k.
// attn[m,n] = sum_{i,j} q[i,j] * k[(m-i)&7, (n-j)&7]
// Block: one channel, one patch-row (8 image rows), all 32 patches along x.
// 256 threads = 32 patches x 8 output rows; each thread computes 8 outputs.
// ---------------------------------------------------------------------------
__global__ void fftattn_k(const float* __restrict__ QKV, float* __restrict__ A,
                          long qkvbs, long abs_)
{
    int b = blockIdx.z;
    int c = blockIdx.y;
    int py = blockIdx.x;             // patch row 0..31
    const float* q = QKV + (long)b * qkvbs + (long)c * NPIX;
    const float* k = QKV + (long)b * qkvbs + (long)(256 + c) * NPIX;
    float* out = A + (long)b * abs_ + (long)c * NPIX;

    __shared__ float qs[8 * 260];
    __shared__ float ks[8 * 260];

    int t = threadIdx.x;             // 0..255
    int rowbase = py * 8;
#pragma unroll
    for (int iy = 0; iy < 8; iy++) {
        qs[iy * 260 + t] = q[(rowbase + iy) * WW + t];
        ks[iy * 260 + t] = k[(rowbase + iy) * WW + t];
    }
    __syncthreads();

    int px = t >> 3;                 // 0..31 patch column
    int m = t & 7;                   // output row within patch
    int base = px * 8;

    float acc[8];
#pragma unroll
    for (int j = 0; j < 8; j++) acc[j] = 0.f;

#pragma unroll
    for (int iy = 0; iy < 8; iy++) {
        float qr[8], kr[8];
        const float* qp = &qs[iy * 260 + base];
        const float* kp = &ks[((m - iy) & 7) * 260 + base];
#pragma unroll
        for (int j = 0; j < 8; j++) { qr[j] = qp[j]; kr[j] = kp[j]; }
#pragma unroll
        for (int jx = 0; jx < 8; jx++)
#pragma unroll
            for (int ix = 0; ix < 8; ix++)
                acc[jx] += qr[ix] * kr[(jx - ix) & 7];
    }

    int gy = rowbase + m;
#pragma unroll
    for (int jx = 0; jx < 8; jx++)
        out[gy * WW + base + jx] = acc[jx];
}

// ---------------------------------------------------------------------------
// Gate: m[c,p] = D[c,p] * D[c+128,p],  c in [0,128)
// ---------------------------------------------------------------------------
__global__ void gate_k(const float* __restrict__ D, float* __restrict__ Y,
                       long dbs, long ybs)
{
    int b = blockIdx.z;
    const float* d = D + (long)b * dbs;
    float* y = Y + (long)b * ybs;
    long i = (long)blockIdx.x * blockDim.x + threadIdx.x;   // 0 .. 128*NPIX-1
    y[i] = d[i] * d[i + 128L * NPIX];
}

// ---------------------------------------------------------------------------

extern "C" void kernel_launch(void* const* d_in, const int* in_sizes, int n_in,
                              void* d_out, int out_size)
{
    const float* x     = (const float*)d_in[0];
    const float* n1w   = (const float*)d_in[1];
    const float* n1b   = (const float*)d_in[2];
    const float* w_h1  = (const float*)d_in[3];
    const float* w_dw1 = (const float*)d_in[4];
    const float* n2w   = (const float*)d_in[5];
    const float* n2b   = (const float*)d_in[6];
    const float* w_p1  = (const float*)d_in[7];
    const float* n3w   = (const float*)d_in[8];
    const float* n3b   = (const float*)d_in[9];
    const float* w_h2  = (const float*)d_in[10];
    const float* b_h2  = (const float*)d_in[11];
    const float* w_dw2 = (const float*)d_in[12];
    const float* w_p2  = (const float*)d_in[13];
    const float* sc1   = (const float*)d_in[14];
    const float* sc2   = (const float*)d_in[15];
    float* out = (float*)d_out;

    float *hn, *hid, *qkv;
    cudaGetSymbolAddress((void**)&hn, s_hn);
    cudaGetSymbolAddress((void**)&hid, s_hidden);
    cudaGetSymbolAddress((void**)&qkv, s_qkv);

    const long N = NPIX;
    dim3 thr(256);

    // 1. h = LN1(x) -> hn [B,128,N]
    ln_k<false><<<dim3(NPIX / 256, 1, BATCH), thr>>>(
        x, n1w, n1b, nullptr, hn, 128, 128 * N, 0, 128 * N);

    // 2. hidden = w_h1 @ h  (768x128) -> hid [B,768,N]
    gemm_k<false, false><<<dim3(NPIX / 64, 768 / 64, BATCH), thr>>>(
        w_h1, hn, nullptr, nullptr, nullptr, hid, 768, 128, 128 * N, 768 * N, 0);

    // 3. qkv = dw3x3(hidden) -> qkv [B,768,N]
    dwconv3_k<<<dim3(NPIX / 256, 768, BATCH), thr>>>(
        hid, w_dw1, qkv, 768 * N, 768 * N);

    // 4. attn = per-patch circular conv(q,k) -> hid[b][0:256]
    fftattn_k<<<dim3(32, 256, BATCH), thr>>>(
        qkv, hid, 768 * N, 768 * N);

    // 5. va = v * LN2(attn) -> hid[b][256:512]
    ln_k<true><<<dim3(NPIX / 256, 1, BATCH), thr>>>(
        hid, n2w, n2b, qkv + 512 * N, hid + 256 * N, 256,
        768 * N, 768 * N, 768 * N);

    // 6. x1 = x + scale1 * (w_p1 @ va)  (128x256) -> out (used as x1)
    gemm_k<false, true><<<dim3(NPIX / 64, 128 / 64, BATCH), thr>>>(
        w_p1, hid + 256 * N, nullptr, x, sc1, out, 128, 256,
        768 * N, 128 * N, 128 * N);

    // 7. h = LN3(x1) -> hn
    ln_k<false><<<dim3(NPIX / 256, 1, BATCH), thr>>>(
        out, n3w, n3b, nullptr, hn, 128, 128 * N, 0, 128 * N);

    // 8. g = w_h2 @ h + b_h2  (256x128) -> qkv[b][0:256]
    gemm_k<true, false><<<dim3(NPIX / 64, 256 / 64, BATCH), thr>>>(
        w_h2, hn, b_h2, nullptr, nullptr, qkv, 256, 128, 128 * N, 768 * N, 0);

    // 9. d = dw3x3(g) (256 ch) -> hid[b][0:256]
    dwconv3_k<<<dim3(NPIX / 256, 256, BATCH), thr>>>(
        qkv, w_dw2, hid, 768 * N, 768 * N);

    // 10. m = d[0:128] * d[128:256] -> hn
    gate_k<<<dim3(128 * NPIX / 256, 1, BATCH), thr>>>(
        hid, hn, 768 * N, 128 * N);

    // 11. out = x1 + scale2 * (w_p2 @ m)  (128x128), in-place residual on out
    gemm_k<false, true><<<dim3(NPIX / 64, 128 / 64, BATCH), thr>>>(
        w_p2, hn, nullptr, out, sc2, out, 128, 128, 128 * N, 128 * N, 128 * N);
}

// round 2
// speedup vs baseline: 2.0304x; 2.0304x over previous
#include <cuda_runtime.h>
#include <cuda_bf16.h>
#include <cstdint>

// ===========================================================================
// NHWC bf16 pipeline with tensor-core (mma.sync bf16) GEMMs.
//   ln1 (NCHW fp32 -> NHWC bf16) -> GEMM1(768) -> dw3x3 -> patchconv+LN2*v
//   -> GEMM2(128, +x resid, fp32 NHWC x1) -> ln3 -> GEMM3(256,+bias)
//   -> dw3x3+gate -> GEMM4(128, +x1 resid, NCHW fp32 out)
// ===========================================================================

#define NPIX 65536           // per image
#define MTOT 131072L         // total pixels (batch 2)

__device__ __align__(16) __nv_bfloat16 g_hn[MTOT * 128];    // LN outs / mgate
__device__ __align__(16) __nv_bfloat16 g_buf1[MTOT * 768];  // hidden / va / g
__device__ __align__(16) __nv_bfloat16 g_buf2[MTOT * 768];  // qkv / x1(fp32)
__device__ __align__(16) __nv_bfloat16 g_wb[180224];        // bf16 weights

__device__ __forceinline__ unsigned pack_bf(float a, float b) {
    __nv_bfloat162 h = __float22bfloat162_rn(make_float2(a, b));
    return *(unsigned*)&h;
}
__device__ __forceinline__ float2 unpack_bf(unsigned u) {
    __nv_bfloat162 h = *(__nv_bfloat162*)&u;
    return make_float2(__bfloat162float(h.x), __bfloat162float(h.y));
}
__device__ __forceinline__ uint32_t smem_u32(const void* p) {
    return (uint32_t)__cvta_generic_to_shared(p);
}

// ---------------------------------------------------------------------------
// Weight conversion fp32 -> bf16 (once per launch; tiny)
// offsets: w_h1 0..98304, w_p1 98304.., w_h2 131072.., w_p2 163840..180224
// ---------------------------------------------------------------------------
__global__ void wcvt_k(const float* __restrict__ w1, const float* __restrict__ w2,
                       const float* __restrict__ w3, const float* __restrict__ w4,
                       __nv_bfloat16* __restrict__ o)
{
    int i = blockIdx.x * 256 + threadIdx.x;
    if (i < 98304)       o[i] = __float2bfloat16(w1[i]);
    else if (i < 131072) o[i] = __float2bfloat16(w2[i - 98304]);
    else if (i < 163840) o[i] = __float2bfloat16(w3[i - 131072]);
    else if (i < 180224) o[i] = __float2bfloat16(w4[i - 163840]);
}

// ---------------------------------------------------------------------------
// LN1: x NCHW fp32 -> y NHWC bf16 (C=128). Pixel-per-thread, smem-staged
// transposed writes.
// ---------------------------------------------------------------------------
__global__ __launch_bounds__(256) void ln1_k(const float* __restrict__ x,
                                             const float* __restrict__ g,
                                             const float* __restrict__ b,
                                             __nv_bfloat16* __restrict__ y)
{
    __shared__ __nv_bfloat16 st[256 * 18];
    int t = threadIdx.x;
    long gp0 = (long)blockIdx.x * 256;
    long gp = gp0 + t;
    int bb = (int)(gp >> 16);
    int p  = (int)(gp & 65535);
    const float* xp = x + (long)bb * 128 * NPIX + p;

    float s = 0.f, s2 = 0.f;
    for (int c = 0; c < 128; c++) {
        float v = xp[(long)c * NPIX];
        s += v; s2 += v * v;
    }
    float m = s * (1.f / 128.f);
    float r = rsqrtf(s2 * (1.f / 128.f) - m * m + 1e-6f);

    for (int c0 = 0; c0 < 128; c0 += 16) {
#pragma unroll
        for (int cc = 0; cc < 16; cc++) {
            float v = xp[(long)(c0 + cc) * NPIX];
            st[t * 18 + cc] = __float2bfloat16((v - m) * r * g[c0 + cc] + b[c0 + cc]);
        }
        __syncthreads();
        for (int it = 0; it < 8; it++) {
            int lin = it * 256 + t;
            int pl = lin >> 3, cw = lin & 7;
            unsigned v = *(unsigned*)&st[pl * 18 + cw * 2];
            *(unsigned*)(y + (gp0 + pl) * 128 + c0 + cw * 2) = v;
        }
        __syncthreads();
    }
}

// ---------------------------------------------------------------------------
// LN3: x1 NHWC fp32 -> y NHWC bf16 (C=128). Warp per pixel.
// ---------------------------------------------------------------------------
__global__ __launch_bounds__(256) void ln3_k(const float* __restrict__ x,
                                             const float* __restrict__ g,
                                             const float* __restrict__ b,
                                             __nv_bfloat16* __restrict__ y)
{
    int t = threadIdx.x, lane = t & 31, w = t >> 5;
    long p = (long)blockIdx.x * 8 + w;
    float4 v = *(const float4*)&x[p * 128 + lane * 4];
    float s = v.x + v.y + v.z + v.w;
    float s2 = v.x * v.x + v.y * v.y + v.z * v.z + v.w * v.w;
#pragma unroll
    for (int o = 16; o; o >>= 1) {
        s  += __shfl_xor_sync(0xffffffffu, s, o);
        s2 += __shfl_xor_sync(0xffffffffu, s2, o);
    }
    float m = s * (1.f / 128.f);
    float r = rsqrtf(s2 * (1.f / 128.f) - m * m + 1e-6f);
    int c = lane * 4;
    float o0 = (v.x - m) * r * g[c]     + b[c];
    float o1 = (v.y - m) * r * g[c + 1] + b[c + 1];
    float o2 = (v.z - m) * r * g[c + 2] + b[c + 2];
    float o3 = (v.w - m) * r * g[c + 3] + b[c + 3];
    uint2 u = make_uint2(pack_bf(o0, o1), pack_bf(o2, o3));
    *(uint2*)(y + p * 128 + c) = u;
}

// ---------------------------------------------------------------------------
// Tensor-core GEMM: Y[m, n] over M=131072 pixels.
//   A: NHWC bf16 activations [M, K]   (K = 128 or 256)
//   B: bf16 weights [Ntot, K]
// EPI 0: bf16 NHWC out
// EPI 1: bf16 NHWC out + bias
// EPI 2: fp32 NHWC out = x_nchw + S[n]*acc      (x NCHW fp32)
// EPI 3: fp32 NCHW out = x1_nhwc + S[n]*acc     (x1 NHWC fp32)
// Block tile 128x128x64, 8 warps (4m x 2n), warp tile 32x64.
// ---------------------------------------------------------------------------
template <int K, int EPI>
__global__ __launch_bounds__(256) void gemm_tc(
    const __nv_bfloat16* __restrict__ A, const __nv_bfloat16* __restrict__ B,
    const float* __restrict__ bias, const float* __restrict__ R,
    const float* __restrict__ S, void* __restrict__ Yv, int Ntot)
{
    constexpr int LDS_ = 72;
    __shared__ __nv_bfloat16 As[128 * LDS_];
    __shared__ __nv_bfloat16 Bs[128 * LDS_];

    int t = threadIdx.x;
    long m0 = (long)blockIdx.x * 128;
    int n0 = blockIdx.y * 128;
    int wid = t >> 5, lane = t & 31;
    int wm = (wid & 3) * 32, wn = (wid >> 2) * 64;

    float acc[2][8][4];
#pragma unroll
    for (int i = 0; i < 2; i++)
#pragma unroll
        for (int j = 0; j < 8; j++)
#pragma unroll
            for (int q = 0; q < 4; q++) acc[i][j][q] = 0.f;

    int lrow = t >> 3, lcol = (t & 7) * 8;

    for (int k0 = 0; k0 < K; k0 += 64) {
#pragma unroll
        for (int pp = 0; pp < 4; pp++) {
            int row = pp * 32 + lrow;
            *(uint4*)&As[row * LDS_ + lcol] =
                *(const uint4*)&A[(m0 + row) * K + k0 + lcol];
            *(uint4*)&Bs[row * LDS_ + lcol] =
                *(const uint4*)&B[(long)(n0 + row) * K + k0 + lcol];
        }
        __syncthreads();
#pragma unroll
        for (int kk = 0; kk < 4; kk++) {
            uint32_t a[2][4], bf[8][2];
#pragma unroll
            for (int mi = 0; mi < 2; mi++) {
                uint32_t addr = smem_u32(
                    &As[(wm + mi * 16 + (lane & 15)) * LDS_ + kk * 16 + (lane >> 4) * 8]);
                asm volatile("ldmatrix.sync.aligned.m8n8.x4.shared.b16 {%0,%1,%2,%3}, [%4];"
                             : "=r"(a[mi][0]), "=r"(a[mi][1]), "=r"(a[mi][2]), "=r"(a[mi][3])
                             : "r"(addr));
            }
#pragma unroll
            for (int nb = 0; nb < 4; nb++) {
                int row = wn + nb * 16 + ((lane >> 4) << 3) + (lane & 7);
                int col = kk * 16 + ((lane >> 3) & 1) * 8;
                uint32_t addr = smem_u32(&Bs[row * LDS_ + col]);
                uint32_t r0, r1, r2, r3;
                asm volatile("ldmatrix.sync.aligned.m8n8.x4.shared.b16 {%0,%1,%2,%3}, [%4];"
                             : "=r"(r0), "=r"(r1), "=r"(r2), "=r"(r3) : "r"(addr));
                bf[nb * 2][0] = r0;     bf[nb * 2][1] = r1;
                bf[nb * 2 + 1][0] = r2; bf[nb * 2 + 1][1] = r3;
            }
#pragma unroll
            for (int mi = 0; mi < 2; mi++)
#pragma unroll
                for (int nj = 0; nj < 8; nj++) {
                    asm volatile(
                        "mma.sync.aligned.m16n8k16.row.col.f32.bf16.bf16.f32 "
                        "{%0,%1,%2,%3}, {%4,%5,%6,%7}, {%8,%9}, {%0,%1,%2,%3};"
                        : "+f"(acc[mi][nj][0]), "+f"(acc[mi][nj][1]),
                          "+f"(acc[mi][nj][2]), "+f"(acc[mi][nj][3])
                        : "r"(a[mi][0]), "r"(a[mi][1]), "r"(a[mi][2]), "r"(a[mi][3]),
                          "r"(bf[nj][0]), "r"(bf[nj][1]));
                }
        }
        __syncthreads();
    }

    int g = lane >> 2, tg = lane & 3;
#pragma unroll
    for (int mi = 0; mi < 2; mi++) {
#pragma unroll
        for (int nj = 0; nj < 8; nj++) {
            int col = n0 + wn + nj * 8 + tg * 2;
#pragma unroll
            for (int half = 0; half < 2; half++) {
                long row = m0 + wm + mi * 16 + g + half * 8;
                float v0 = acc[mi][nj][half * 2];
                float v1 = acc[mi][nj][half * 2 + 1];
                if (EPI == 0 || EPI == 1) {
                    if (EPI == 1) { v0 += bias[col]; v1 += bias[col + 1]; }
                    *(unsigned*)((__nv_bfloat16*)Yv + row * Ntot + col) = pack_bf(v0, v1);
                } else if (EPI == 2) {
                    int bb = (int)(row >> 16), p = (int)(row & 65535);
                    float r0 = R[((long)(bb * 128 + col)) * NPIX + p];
                    float r1 = R[((long)(bb * 128 + col + 1)) * NPIX + p];
                    float2 o = make_float2(r0 + S[col] * v0, r1 + S[col + 1] * v1);
                    *(float2*)((float*)Yv + row * 128 + col) = o;
                } else {  // EPI 3
                    int bb = (int)(row >> 16), p = (int)(row & 65535);
                    float2 rr = *(const float2*)&R[row * 128 + col];
                    ((float*)Yv)[((long)(bb * 128 + col)) * NPIX + p]     = rr.x + S[col] * v0;
                    ((float*)Yv)[((long)(bb * 128 + col + 1)) * NPIX + p] = rr.y + S[col + 1] * v1;
                }
            }
        }
    }
}

// ---------------------------------------------------------------------------
// Depthwise 3x3 NHWC bf16, SAME padding. Tile 8x32 pixels x 16 channels.
// GATE: C=256 input, computes dw on ch c0 and c0+128 and writes their product
// to a 128-channel output (the FFN gate).
// ---------------------------------------------------------------------------
template <int C, bool GATE>
__global__ __launch_bounds__(256) void dw_k(const __nv_bfloat16* __restrict__ X,
                                            const float* __restrict__ Wd,
                                            __nv_bfloat16* __restrict__ Y)
{
    constexpr int NH = GATE ? 2 : 1;
    __shared__ unsigned in_s[NH][10 * 34 * 9];
    __shared__ float w_s[NH][9][16];

    int t = threadIdx.x;
    int bx = blockIdx.x;
    int ty = bx >> 3, tx = bx & 7;
    int c0 = blockIdx.y * 16;
    long ibase = (long)blockIdx.z * NPIX;

    for (int i = t; i < NH * 144; i += 256) {
        int h = i / 144, j = i % 144, ch = j / 9, tap = j % 9;
        w_s[h][tap][ch] = Wd[(c0 + h * 128 + ch) * 9 + tap];
    }
    for (int lin = t; lin < 340; lin += 256) {
        int ry = lin / 34, rx = lin % 34;
        int yy = ty * 8 + ry - 1, xx = tx * 32 + rx - 1;
        bool ok = (yy >= 0 && yy < 256 && xx >= 0 && xx < 256);
#pragma unroll
        for (int h = 0; h < NH; h++) {
            uint4 v0 = make_uint4(0, 0, 0, 0), v1 = make_uint4(0, 0, 0, 0);
            if (ok) {
                const uint4* src = (const uint4*)(X + (ibase + yy * 256 + xx) * C + c0 + h * 128);
                v0 = src[0]; v1 = src[1];
            }
            unsigned* d = &in_s[h][(ry * 34 + rx) * 9];
            d[0] = v0.x; d[1] = v0.y; d[2] = v0.z; d[3] = v0.w;
            d[4] = v1.x; d[5] = v1.y; d[6] = v1.z; d[7] = v1.w;
        }
    }
    __syncthreads();

    int oy = t >> 5, ox = t & 31;
    float2 acc[NH][8];
#pragma unroll
    for (int h = 0; h < NH; h++)
#pragma unroll
        for (int cc = 0; cc < 8; cc++) acc[h][cc] = make_float2(0.f, 0.f);

#pragma unroll
    for (int ky = 0; ky < 3; ky++)
#pragma unroll
        for (int kx = 0; kx < 3; kx++) {
            int base = ((oy + ky) * 34 + (ox + kx)) * 9;
#pragma unroll
            for (int h = 0; h < NH; h++)
#pragma unroll
                for (int cc = 0; cc < 8; cc++) {
                    float2 v = unpack_bf(in_s[h][base + cc]);
                    acc[h][cc].x += v.x * w_s[h][ky * 3 + kx][cc * 2];
                    acc[h][cc].y += v.y * w_s[h][ky * 3 + kx][cc * 2 + 1];
                }
        }

    long opix = ibase + (ty * 8 + oy) * 256 + (tx * 32 + ox);
    if (!GATE) {
        unsigned* dst = (unsigned*)(Y + opix * C + c0);
#pragma unroll
        for (int cc = 0; cc < 8; cc++)
            dst[cc] = pack_bf(acc[0][cc].x, acc[0][cc].y);
    } else {
        unsigned* dst = (unsigned*)(Y + opix * 128 + c0);
#pragma unroll
        for (int cc = 0; cc < 8; cc++)
            dst[cc] = pack_bf(acc[0][cc].x * acc[1][cc].x, acc[0][cc].y * acc[1][cc].y);
    }
}

// ---------------------------------------------------------------------------
// Patch attention (8x8 circular conv of q,k) fused with LN2 and * v.
// Block = one 8x8 patch, all 256 channels. qkv NHWC bf16 [pix][768].
// Dynamic smem: q_s/k_s (uint bf16x2, 32KB each) aliased by attn fp32
// (stride 257 to dodge bank conflicts).
// ---------------------------------------------------------------------------
__global__ __launch_bounds__(256) void attn_k(const __nv_bfloat16* __restrict__ qkv,
                                              const float* __restrict__ g2,
                                              const float* __restrict__ b2,
                                              __nv_bfloat16* __restrict__ va)
{
    extern __shared__ char smdyn[];
    unsigned* q_s = (unsigned*)smdyn;        // [64*128]
    unsigned* k_s = q_s + 64 * 128;          // [64*128]
    float* attn = (float*)smdyn;             // [64*257] (alias, used post-sync)
    __shared__ float red[64][4][2];

    int t = threadIdx.x;
    int bx = blockIdx.x;
    int py = bx >> 5, px = bx & 31;
    long ibase = (long)blockIdx.z * NPIX;

    for (int r = 0; r < 8; r++) {
        int lin = r * 256 + t;
        int pix = lin >> 5, c4 = lin & 31;
        long gpix = ibase + (py * 8 + (pix >> 3)) * 256 + px * 8 + (pix & 7);
        ((uint4*)q_s)[pix * 32 + c4] = __ldg((const uint4*)(qkv + gpix * 768) + c4);
        ((uint4*)k_s)[pix * 32 + c4] = __ldg((const uint4*)(qkv + gpix * 768 + 256) + c4);
    }
    __syncthreads();

    int cp = t & 127;
    int mg = t >> 7;
    float acc[4][8][2];
#pragma unroll
    for (int a = 0; a < 4; a++)
#pragma unroll
        for (int b = 0; b < 8; b++) { acc[a][b][0] = 0.f; acc[a][b][1] = 0.f; }

#pragma unroll
    for (int i = 0; i < 8; i++) {
        float qv[8][2];
#pragma unroll
        for (int jx = 0; jx < 8; jx++) {
            float2 v = unpack_bf(q_s[(i * 8 + jx) * 128 + cp]);
            qv[jx][0] = v.x; qv[jx][1] = v.y;
        }
#pragma unroll
        for (int mi = 0; mi < 4; mi++) {
            int m = mg + 2 * mi;
            int kr = (m - i) & 7;
            float kv[8][2];
#pragma unroll
            for (int j = 0; j < 8; j++) {
                float2 v = unpack_bf(k_s[(kr * 8 + j) * 128 + cp]);
                kv[j][0] = v.x; kv[j][1] = v.y;
            }
#pragma unroll
            for (int jo = 0; jo < 8; jo++)
#pragma unroll
                for (int jx = 0; jx < 8; jx++) {
                    int jk = (jo - jx) & 7;
                    acc[mi][jo][0] += qv[jx][0] * kv[jk][0];
                    acc[mi][jo][1] += qv[jx][1] * kv[jk][1];
                }
        }
    }
    __syncthreads();   // q_s/k_s reads complete; safe to alias

#pragma unroll
    for (int mi = 0; mi < 4; mi++) {
        int m = mg + 2 * mi;
#pragma unroll
        for (int jo = 0; jo < 8; jo++) {
            attn[(m * 8 + jo) * 257 + 2 * cp]     = acc[mi][jo][0];
            attn[(m * 8 + jo) * 257 + 2 * cp + 1] = acc[mi][jo][1];
        }
    }
    __syncthreads();

    // LN2 over 256 channels per pixel, then * v, write bf16 NHWC
    int pix = t >> 2, q4 = t & 3;
    const float* ap = attn + pix * 257 + q4 * 64;
    float s = 0.f, s2 = 0.f;
#pragma unroll
    for (int i = 0; i < 64; i++) { float v = ap[i]; s += v; s2 += v * v; }
    red[pix][q4][0] = s; red[pix][q4][1] = s2;
    __syncthreads();
    s  = red[pix][0][0] + red[pix][1][0] + red[pix][2][0] + red[pix][3][0];
    s2 = red[pix][0][1] + red[pix][1][1] + red[pix][2][1] + red[pix][3][1];
    float m = s * (1.f / 256.f);
    float r = rsqrtf(s2 * (1.f / 256.f) - m * m + 1e-6f);

    long gpix = ibase + (py * 8 + (pix >> 3)) * 256 + px * 8 + (pix & 7);
    const __nv_bfloat16* vp = qkv + gpix * 768 + 512 + q4 * 64;
    __nv_bfloat16* op = va + gpix * 256 + q4 * 64;
#pragma unroll
    for (int i = 0; i < 64; i += 2) {
        int c = q4 * 64 + i;
        float a0 = (ap[i] - m) * r * __ldg(g2 + c) + __ldg(b2 + c);
        float a1 = (ap[i + 1] - m) * r * __ldg(g2 + c + 1) + __ldg(b2 + c + 1);
        float2 v = unpack_bf(*(const unsigned*)(vp + i));
        *(unsigned*)(op + i) = pack_bf(a0 * v.x, a1 * v.y);
    }
}

// ---------------------------------------------------------------------------

extern "C" void kernel_launch(void* const* d_in, const int* in_sizes, int n_in,
                              void* d_out, int out_size)
{
    const float* x     = (const float*)d_in[0];
    const float* n1w   = (const float*)d_in[1];
    const float* n1b   = (const float*)d_in[2];
    const float* w_h1  = (const float*)d_in[3];
    const float* w_dw1 = (const float*)d_in[4];
    const float* n2w   = (const float*)d_in[5];
    const float* n2b   = (const float*)d_in[6];
    const float* w_p1  = (const float*)d_in[7];
    const float* n3w   = (const float*)d_in[8];
    const float* n3b   = (const float*)d_in[9];
    const float* w_h2  = (const float*)d_in[10];
    const float* b_h2  = (const float*)d_in[11];
    const float* w_dw2 = (const float*)d_in[12];
    const float* w_p2  = (const float*)d_in[13];
    const float* sc1   = (const float*)d_in[14];
    const float* sc2   = (const float*)d_in[15];
    float* out = (float*)d_out;

    __nv_bfloat16 *hn, *buf1, *buf2, *wb;
    cudaGetSymbolAddress((void**)&hn,   g_hn);
    cudaGetSymbolAddress((void**)&buf1, g_buf1);
    cudaGetSymbolAddress((void**)&buf2, g_buf2);
    cudaGetSymbolAddress((void**)&wb,   g_wb);
    float* x1f = (float*)buf2;

    cudaFuncSetAttribute(attn_k, cudaFuncAttributeMaxDynamicSharedMemorySize, 65792);

    // weights -> bf16
    wcvt_k<<<704, 256>>>(w_h1, w_p1, w_h2, w_p2, wb);

    // 1. LN1: x NCHW -> hn NHWC bf16
    ln1_k<<<512, 256>>>(x, n1w, n1b, hn);

    // 2. hidden = hn @ w_h1^T  -> buf1 [M,768] bf16
    gemm_tc<128, 0><<<dim3(1024, 6), 256>>>(hn, wb, nullptr, nullptr, nullptr, buf1, 768);

    // 3. qkv = dw3x3(hidden) -> buf2 [M,768] bf16
    dw_k<768, false><<<dim3(256, 48, 2), 256>>>(buf1, w_dw1, buf2);

    // 4. va = v * LN2(patchconv(q,k)) -> buf1 [M,256] bf16
    attn_k<<<dim3(1024, 1, 2), 256, 65792>>>(buf2, n2w, n2b, buf1);

    // 5. x1 = x + scale1 * (va @ w_p1^T) -> buf2 as fp32 NHWC [M,128]
    gemm_tc<256, 2><<<dim3(1024, 1), 256>>>(buf1, wb + 98304, nullptr, x, sc1, x1f, 128);

    // 6. LN3: x1 -> hn bf16 NHWC
    ln3_k<<<16384, 256>>>(x1f, n3w, n3b, hn);

    // 7. g = hn @ w_h2^T + b_h2 -> buf1 [M,256] bf16
    gemm_tc<128, 1><<<dim3(1024, 2), 256>>>(hn, wb + 131072, b_h2, nullptr, nullptr, buf1, 256);

    // 8. mgate = dw(g)[0:128] * dw(g)[128:256] -> hn [M,128] bf16
    dw_k<256, true><<<dim3(256, 8, 2), 256>>>(buf1, w_dw2, hn);

    // 9. out = x1 + scale2 * (mgate @ w_p2^T) -> d_out NCHW fp32
    gemm_tc<128, 3><<<dim3(1024, 1), 256>>>(hn, wb + 163840, nullptr, x1f, sc2, out, 128);
}

// round 5
// speedup vs baseline: 2.7216x; 1.3404x over previous
#include <cuda_runtime.h>
#include <cuda_bf16.h>
#include <cstdint>

// ===========================================================================
// NHWC bf16 pipeline with tensor-core (mma.sync bf16) GEMMs.
//   ln1 (NCHW fp32 -> NHWC bf16) -> GEMM1(768) -> dw3x3 -> patchconv+LN2*v
//   -> GEMM2(128, +x resid, fp32 NHWC x1) -> ln3 -> GEMM3(256,+bias)
//   -> dw3x3+gate -> GEMM4(128, +x1 resid, NCHW fp32 out)
// R3: dwconv rewritten with channel-slab smem + register sliding window
//     (9 LDS/thread instead of 72).
// ===========================================================================

#define NPIX 65536           // per image
#define MTOT 131072L         // total pixels (batch 2)

__device__ __align__(16) __nv_bfloat16 g_hn[MTOT * 128];    // LN outs / mgate
__device__ __align__(16) __nv_bfloat16 g_buf1[MTOT * 768];  // hidden / va / g
__device__ __align__(16) __nv_bfloat16 g_buf2[MTOT * 768];  // qkv / x1(fp32)
__device__ __align__(16) __nv_bfloat16 g_wb[180224];        // bf16 weights

__device__ __forceinline__ unsigned pack_bf(float a, float b) {
    __nv_bfloat162 h = __float22bfloat162_rn(make_float2(a, b));
    return *(unsigned*)&h;
}
__device__ __forceinline__ float2 unpack_bf(unsigned u) {
    __nv_bfloat162 h = *(__nv_bfloat162*)&u;
    return make_float2(__bfloat162float(h.x), __bfloat162float(h.y));
}
__device__ __forceinline__ uint32_t smem_u32(const void* p) {
    return (uint32_t)__cvta_generic_to_shared(p);
}

// ---------------------------------------------------------------------------
// Weight conversion fp32 -> bf16 (once per launch; tiny)
// ---------------------------------------------------------------------------
__global__ void wcvt_k(const float* __restrict__ w1, const float* __restrict__ w2,
                       const float* __restrict__ w3, const float* __restrict__ w4,
                       __nv_bfloat16* __restrict__ o)
{
    int i = blockIdx.x * 256 + threadIdx.x;
    if (i < 98304)       o[i] = __float2bfloat16(w1[i]);
    else if (i < 131072) o[i] = __float2bfloat16(w2[i - 98304]);
    else if (i < 163840) o[i] = __float2bfloat16(w3[i - 131072]);
    else if (i < 180224) o[i] = __float2bfloat16(w4[i - 163840]);
}

// ---------------------------------------------------------------------------
// LN1: x NCHW fp32 -> y NHWC bf16 (C=128).
// ---------------------------------------------------------------------------
__global__ __launch_bounds__(256) void ln1_k(const float* __restrict__ x,
                                             const float* __restrict__ g,
                                             const float* __restrict__ b,
                                             __nv_bfloat16* __restrict__ y)
{
    __shared__ __nv_bfloat16 st[256 * 18];
    int t = threadIdx.x;
    long gp0 = (long)blockIdx.x * 256;
    long gp = gp0 + t;
    int bb = (int)(gp >> 16);
    int p  = (int)(gp & 65535);
    const float* xp = x + (long)bb * 128 * NPIX + p;

    float s = 0.f, s2 = 0.f;
    for (int c = 0; c < 128; c++) {
        float v = xp[(long)c * NPIX];
        s += v; s2 += v * v;
    }
    float m = s * (1.f / 128.f);
    float r = rsqrtf(s2 * (1.f / 128.f) - m * m + 1e-6f);

    for (int c0 = 0; c0 < 128; c0 += 16) {
#pragma unroll
        for (int cc = 0; cc < 16; cc++) {
            float v = xp[(long)(c0 + cc) * NPIX];
            st[t * 18 + cc] = __float2bfloat16((v - m) * r * g[c0 + cc] + b[c0 + cc]);
        }
        __syncthreads();
        for (int it = 0; it < 8; it++) {
            int lin = it * 256 + t;
            int pl = lin >> 3, cw = lin & 7;
            unsigned v = *(unsigned*)&st[pl * 18 + cw * 2];
            *(unsigned*)(y + (gp0 + pl) * 128 + c0 + cw * 2) = v;
        }
        __syncthreads();
    }
}

// ---------------------------------------------------------------------------
// LN3: x1 NHWC fp32 -> y NHWC bf16 (C=128). Warp per pixel.
// ---------------------------------------------------------------------------
__global__ __launch_bounds__(256) void ln3_k(const float* __restrict__ x,
                                             const float* __restrict__ g,
                                             const float* __restrict__ b,
                                             __nv_bfloat16* __restrict__ y)
{
    int t = threadIdx.x, lane = t & 31, w = t >> 5;
    long p = (long)blockIdx.x * 8 + w;
    float4 v = *(const float4*)&x[p * 128 + lane * 4];
    float s = v.x + v.y + v.z + v.w;
    float s2 = v.x * v.x + v.y * v.y + v.z * v.z + v.w * v.w;
#pragma unroll
    for (int o = 16; o; o >>= 1) {
        s  += __shfl_xor_sync(0xffffffffu, s, o);
        s2 += __shfl_xor_sync(0xffffffffu, s2, o);
    }
    float m = s * (1.f / 128.f);
    float r = rsqrtf(s2 * (1.f / 128.f) - m * m + 1e-6f);
    int c = lane * 4;
    float o0 = (v.x - m) * r * g[c]     + b[c];
    float o1 = (v.y - m) * r * g[c + 1] + b[c + 1];
    float o2 = (v.z - m) * r * g[c + 2] + b[c + 2];
    float o3 = (v.w - m) * r * g[c + 3] + b[c + 3];
    uint2 u = make_uint2(pack_bf(o0, o1), pack_bf(o2, o3));
    *(uint2*)(y + p * 128 + c) = u;
}

// ---------------------------------------------------------------------------
// Tensor-core GEMM (unchanged from R2).
// ---------------------------------------------------------------------------
template <int K, int EPI>
__global__ __launch_bounds__(256) void gemm_tc(
    const __nv_bfloat16* __restrict__ A, const __nv_bfloat16* __restrict__ B,
    const float* __restrict__ bias, const float* __restrict__ R,
    const float* __restrict__ S, void* __restrict__ Yv, int Ntot)
{
    constexpr int LDS_ = 72;
    __shared__ __nv_bfloat16 As[128 * LDS_];
    __shared__ __nv_bfloat16 Bs[128 * LDS_];

    int t = threadIdx.x;
    long m0 = (long)blockIdx.x * 128;
    int n0 = blockIdx.y * 128;
    int wid = t >> 5, lane = t & 31;
    int wm = (wid & 3) * 32, wn = (wid >> 2) * 64;

    float acc[2][8][4];
#pragma unroll
    for (int i = 0; i < 2; i++)
#pragma unroll
        for (int j = 0; j < 8; j++)
#pragma unroll
            for (int q = 0; q < 4; q++) acc[i][j][q] = 0.f;

    int lrow = t >> 3, lcol = (t & 7) * 8;

    for (int k0 = 0; k0 < K; k0 += 64) {
#pragma unroll
        for (int pp = 0; pp < 4; pp++) {
            int row = pp * 32 + lrow;
            *(uint4*)&As[row * LDS_ + lcol] =
                *(const uint4*)&A[(m0 + row) * K + k0 + lcol];
            *(uint4*)&Bs[row * LDS_ + lcol] =
                *(const uint4*)&B[(long)(n0 + row) * K + k0 + lcol];
        }
        __syncthreads();
#pragma unroll
        for (int kk = 0; kk < 4; kk++) {
            uint32_t a[2][4], bf[8][2];
#pragma unroll
            for (int mi = 0; mi < 2; mi++) {
                uint32_t addr = smem_u32(
                    &As[(wm + mi * 16 + (lane & 15)) * LDS_ + kk * 16 + (lane >> 4) * 8]);
                asm volatile("ldmatrix.sync.aligned.m8n8.x4.shared.b16 {%0,%1,%2,%3}, [%4];"
                             : "=r"(a[mi][0]), "=r"(a[mi][1]), "=r"(a[mi][2]), "=r"(a[mi][3])
                             : "r"(addr));
            }
#pragma unroll
            for (int nb = 0; nb < 4; nb++) {
                int row = wn + nb * 16 + ((lane >> 4) << 3) + (lane & 7);
                int col = kk * 16 + ((lane >> 3) & 1) * 8;
                uint32_t addr = smem_u32(&Bs[row * LDS_ + col]);
                uint32_t r0, r1, r2, r3;
                asm volatile("ldmatrix.sync.aligned.m8n8.x4.shared.b16 {%0,%1,%2,%3}, [%4];"
                             : "=r"(r0), "=r"(r1), "=r"(r2), "=r"(r3) : "r"(addr));
                bf[nb * 2][0] = r0;     bf[nb * 2][1] = r1;
                bf[nb * 2 + 1][0] = r2; bf[nb * 2 + 1][1] = r3;
            }
#pragma unroll
            for (int mi = 0; mi < 2; mi++)
#pragma unroll
                for (int nj = 0; nj < 8; nj++) {
                    asm volatile(
                        "mma.sync.aligned.m16n8k16.row.col.f32.bf16.bf16.f32 "
                        "{%0,%1,%2,%3}, {%4,%5,%6,%7}, {%8,%9}, {%0,%1,%2,%3};"
                        : "+f"(acc[mi][nj][0]), "+f"(acc[mi][nj][1]),
                          "+f"(acc[mi][nj][2]), "+f"(acc[mi][nj][3])
                        : "r"(a[mi][0]), "r"(a[mi][1]), "r"(a[mi][2]), "r"(a[mi][3]),
                          "r"(bf[nj][0]), "r"(bf[nj][1]));
                }
        }
        __syncthreads();
    }

    int g = lane >> 2, tg = lane & 3;
#pragma unroll
    for (int mi = 0; mi < 2; mi++) {
#pragma unroll
        for (int nj = 0; nj < 8; nj++) {
            int col = n0 + wn + nj * 8 + tg * 2;
#pragma unroll
            for (int half = 0; half < 2; half++) {
                long row = m0 + wm + mi * 16 + g + half * 8;
                float v0 = acc[mi][nj][half * 2];
                float v1 = acc[mi][nj][half * 2 + 1];
                if (EPI == 0 || EPI == 1) {
                    if (EPI == 1) { v0 += bias[col]; v1 += bias[col + 1]; }
                    *(unsigned*)((__nv_bfloat16*)Yv + row * Ntot + col) = pack_bf(v0, v1);
                } else if (EPI == 2) {
                    int bb = (int)(row >> 16), p = (int)(row & 65535);
                    float r0 = R[((long)(bb * 128 + col)) * NPIX + p];
                    float r1 = R[((long)(bb * 128 + col + 1)) * NPIX + p];
                    float2 o = make_float2(r0 + S[col] * v0, r1 + S[col + 1] * v1);
                    *(float2*)((float*)Yv + row * 128 + col) = o;
                } else {  // EPI 3
                    int bb = (int)(row >> 16), p = (int)(row & 65535);
                    float2 rr = *(const float2*)&R[row * 128 + col];
                    ((float*)Yv)[((long)(bb * 128 + col)) * NPIX + p]     = rr.x + S[col] * v0;
                    ((float*)Yv)[((long)(bb * 128 + col + 1)) * NPIX + p] = rr.y + S[col + 1] * v1;
                }
            }
        }
    }
}

// ---------------------------------------------------------------------------
// Depthwise 3x3 NHWC bf16, SAME padding. Tile 8x32 px, 16 channels per block.
// Channel-slab smem: in_s[h][cg][row*36 + col], cg = 2-channel uint group.
// Each thread: one output row, 8 consecutive x, one cg. Sliding window:
// per ky a 10-wide strip loaded with LDS.128/.128/.64 (3 LDS), 8 outputs.
// Slab stride 364 words: cg*12 mod 32 distinct -> conflict-lean LDS.128.
// GATE: two channel halves, writes their product (FFN gate).
// ---------------------------------------------------------------------------
template <int C, bool GATE>
__global__ __launch_bounds__(256) void dw_k(const __nv_bfloat16* __restrict__ X,
                                            const float* __restrict__ Wd,
                                            __nv_bfloat16* __restrict__ Y)
{
    constexpr int NH = GATE ? 2 : 1;
    __shared__ unsigned in_s[NH][8][364];   // 8 slabs x (10 rows * 36 + pad)
    __shared__ float w_s[NH][9][16];

    int t = threadIdx.x;
    int bx = blockIdx.x;
    int ty = bx >> 3, tx = bx & 7;
    int c0 = blockIdx.y * 16;
    long ibase = (long)blockIdx.z * NPIX;

    for (int i = t; i < NH * 144; i += 256) {
        int h = i / 144, j = i % 144, ch = j / 9, tap = j % 9;
        w_s[h][tap][ch] = Wd[(c0 + h * 128 + ch) * 9 + tap];
    }
    // stage 10x34 halo tile into channel slabs
    for (int lin = t; lin < 340; lin += 256) {
        int ry = lin / 34, rx = lin % 34;
        int yy = ty * 8 + ry - 1, xx = tx * 32 + rx - 1;
        bool ok = (yy >= 0 && yy < 256 && xx >= 0 && xx < 256);
        int po = ry * 36 + rx;
#pragma unroll
        for (int h = 0; h < NH; h++) {
            uint4 v0 = make_uint4(0, 0, 0, 0), v1 = make_uint4(0, 0, 0, 0);
            if (ok) {
                const uint4* src = (const uint4*)(X + (ibase + yy * 256 + xx) * C + c0 + h * 128);
                v0 = src[0]; v1 = src[1];
            }
            in_s[h][0][po] = v0.x; in_s[h][1][po] = v0.y;
            in_s[h][2][po] = v0.z; in_s[h][3][po] = v0.w;
            in_s[h][4][po] = v1.x; in_s[h][5][po] = v1.y;
            in_s[h][6][po] = v1.z; in_s[h][7][po] = v1.w;
        }
    }
    __syncthreads();

    int oy = t >> 5;            // 0..7 output row
    int xg = (t >> 3) & 3;      // 0..3 x-group (8 px each)
    int cg = t & 7;             // 0..7 channel pair
    int ox0 = xg * 8;

    float2 acc[NH][8];
#pragma unroll
    for (int h = 0; h < NH; h++)
#pragma unroll
        for (int j = 0; j < 8; j++) acc[h][j] = make_float2(0.f, 0.f);

#pragma unroll
    for (int h = 0; h < NH; h++) {
        float2 wr[9];
#pragma unroll
        for (int tap = 0; tap < 9; tap++)
            wr[tap] = make_float2(w_s[h][tap][cg * 2], w_s[h][tap][cg * 2 + 1]);

#pragma unroll
        for (int ky = 0; ky < 3; ky++) {
            const unsigned* rp = &in_s[h][cg][(oy + ky) * 36 + ox0];
            uint4 va_ = *(const uint4*)rp;
            uint4 vb_ = *(const uint4*)(rp + 4);
            uint2 vc_ = *(const uint2*)(rp + 8);
            float2 f[10];
            f[0] = unpack_bf(va_.x); f[1] = unpack_bf(va_.y);
            f[2] = unpack_bf(va_.z); f[3] = unpack_bf(va_.w);
            f[4] = unpack_bf(vb_.x); f[5] = unpack_bf(vb_.y);
            f[6] = unpack_bf(vb_.z); f[7] = unpack_bf(vb_.w);
            f[8] = unpack_bf(vc_.x); f[9] = unpack_bf(vc_.y);
#pragma unroll
            for (int kx = 0; kx < 3; kx++) {
                float2 w = wr[ky * 3 + kx];
#pragma unroll
                for (int j = 0; j < 8; j++) {
                    acc[h][j].x += f[j + kx].x * w.x;
                    acc[h][j].y += f[j + kx].y * w.y;
                }
            }
        }
    }

    long opix = ibase + (ty * 8 + oy) * 256 + tx * 32 + ox0;
    if (!GATE) {
#pragma unroll
        for (int j = 0; j < 8; j++)
            *(unsigned*)(Y + (opix + j) * C + c0 + cg * 2) =
                pack_bf(acc[0][j].x, acc[0][j].y);
    } else {
#pragma unroll
        for (int j = 0; j < 8; j++)
            *(unsigned*)(Y + (opix + j) * 128 + c0 + cg * 2) =
                pack_bf(acc[0][j].x * acc[1][j].x, acc[0][j].y * acc[1][j].y);
    }
}

// ---------------------------------------------------------------------------
// Patch attention (8x8 circular conv of q,k) fused with LN2 and * v.
// (unchanged from R2)
// ---------------------------------------------------------------------------
__global__ __launch_bounds__(256) void attn_k(const __nv_bfloat16* __restrict__ qkv,
                                              const float* __restrict__ g2,
                                              const float* __restrict__ b2,
                                              __nv_bfloat16* __restrict__ va)
{
    extern __shared__ char smdyn[];
    unsigned* q_s = (unsigned*)smdyn;        // [64*128]
    unsigned* k_s = q_s + 64 * 128;          // [64*128]
    float* attn = (float*)smdyn;             // [64*257] alias
    __shared__ float red[64][4][2];

    int t = threadIdx.x;
    int bx = blockIdx.x;
    int py = bx >> 5, px = bx & 31;
    long ibase = (long)blockIdx.z * NPIX;

    for (int r = 0; r < 8; r++) {
        int lin = r * 256 + t;
        int pix = lin >> 5, c4 = lin & 31;
        long gpix = ibase + (py * 8 + (pix >> 3)) * 256 + px * 8 + (pix & 7);
        ((uint4*)q_s)[pix * 32 + c4] = __ldg((const uint4*)(qkv + gpix * 768) + c4);
        ((uint4*)k_s)[pix * 32 + c4] = __ldg((const uint4*)(qkv + gpix * 768 + 256) + c4);
    }
    __syncthreads();

    int cp = t & 127;
    int mg = t >> 7;
    float acc[4][8][2];
#pragma unroll
    for (int a = 0; a < 4; a++)
#pragma unroll
        for (int b = 0; b < 8; b++) { acc[a][b][0] = 0.f; acc[a][b][1] = 0.f; }

#pragma unroll
    for (int i = 0; i < 8; i++) {
        float qv[8][2];
#pragma unroll
        for (int jx = 0; jx < 8; jx++) {
            float2 v = unpack_bf(q_s[(i * 8 + jx) * 128 + cp]);
            qv[jx][0] = v.x; qv[jx][1] = v.y;
        }
#pragma unroll
        for (int mi = 0; mi < 4; mi++) {
            int m = mg + 2 * mi;
            int kr = (m - i) & 7;
            float kv[8][2];
#pragma unroll
            for (int j = 0; j < 8; j++) {
                float2 v = unpack_bf(k_s[(kr * 8 + j) * 128 + cp]);
                kv[j][0] = v.x; kv[j][1] = v.y;
            }
#pragma unroll
            for (int jo = 0; jo < 8; jo++)
#pragma unroll
                for (int jx = 0; jx < 8; jx++) {
                    int jk = (jo - jx) & 7;
                    acc[mi][jo][0] += qv[jx][0] * kv[jk][0];
                    acc[mi][jo][1] += qv[jx][1] * kv[jk][1];
                }
        }
    }
    __syncthreads();

#pragma unroll
    for (int mi = 0; mi < 4; mi++) {
        int m = mg + 2 * mi;
#pragma unroll
        for (int jo = 0; jo < 8; jo++) {
            attn[(m * 8 + jo) * 257 + 2 * cp]     = acc[mi][jo][0];
            attn[(m * 8 + jo) * 257 + 2 * cp + 1] = acc[mi][jo][1];
        }
    }
    __syncthreads();

    int pix = t >> 2, q4 = t & 3;
    const float* ap = attn + pix * 257 + q4 * 64;
    float s = 0.f, s2 = 0.f;
#pragma unroll
    for (int i = 0; i < 64; i++) { float v = ap[i]; s += v; s2 += v * v; }
    red[pix][q4][0] = s; red[pix][q4][1] = s2;
    __syncthreads();
    s  = red[pix][0][0] + red[pix][1][0] + red[pix][2][0] + red[pix][3][0];
    s2 = red[pix][0][1] + red[pix][1][1] + red[pix][2][1] + red[pix][3][1];
    float m = s * (1.f / 256.f);
    float r = rsqrtf(s2 * (1.f / 256.f) - m * m + 1e-6f);

    long gpix = ibase + (py * 8 + (pix >> 3)) * 256 + px * 8 + (pix & 7);
    const __nv_bfloat16* vp = qkv + gpix * 768 + 512 + q4 * 64;
    __nv_bfloat16* op = va + gpix * 256 + q4 * 64;
#pragma unroll
    for (int i = 0; i < 64; i += 2) {
        int c = q4 * 64 + i;
        float a0 = (ap[i] - m) * r * __ldg(g2 + c) + __ldg(b2 + c);
        float a1 = (ap[i + 1] - m) * r * __ldg(g2 + c + 1) + __ldg(b2 + c + 1);
        float2 v = unpack_bf(*(const unsigned*)(vp + i));
        *(unsigned*)(op + i) = pack_bf(a0 * v.x, a1 * v.y);
    }
}

// ---------------------------------------------------------------------------

extern "C" void kernel_launch(void* const* d_in, const int* in_sizes, int n_in,
                              void* d_out, int out_size)
{
    const float* x     = (const float*)d_in[0];
    const float* n1w   = (const float*)d_in[1];
    const float* n1b   = (const float*)d_in[2];
    const float* w_h1  = (const float*)d_in[3];
    const float* w_dw1 = (const float*)d_in[4];
    const float* n2w   = (const float*)d_in[5];
    const float* n2b   = (const float*)d_in[6];
    const float* w_p1  = (const float*)d_in[7];
    const float* n3w   = (const float*)d_in[8];
    const float* n3b   = (const float*)d_in[9];
    const float* w_h2  = (const float*)d_in[10];
    const float* b_h2  = (const float*)d_in[11];
    const float* w_dw2 = (const float*)d_in[12];
    const float* w_p2  = (const float*)d_in[13];
    const float* sc1   = (const float*)d_in[14];
    const float* sc2   = (const float*)d_in[15];
    float* out = (float*)d_out;

    __nv_bfloat16 *hn, *buf1, *buf2, *wb;
    cudaGetSymbolAddress((void**)&hn,   g_hn);
    cudaGetSymbolAddress((void**)&buf1, g_buf1);
    cudaGetSymbolAddress((void**)&buf2, g_buf2);
    cudaGetSymbolAddress((void**)&wb,   g_wb);
    float* x1f = (float*)buf2;

    cudaFuncSetAttribute(attn_k, cudaFuncAttributeMaxDynamicSharedMemorySize, 65792);

    // weights -> bf16
    wcvt_k<<<704, 256>>>(w_h1, w_p1, w_h2, w_p2, wb);

    // 1. LN1: x NCHW -> hn NHWC bf16
    ln1_k<<<512, 256>>>(x, n1w, n1b, hn);

    // 2. hidden = hn @ w_h1^T  -> buf1 [M,768] bf16
    gemm_tc<128, 0><<<dim3(1024, 6), 256>>>(hn, wb, nullptr, nullptr, nullptr, buf1, 768);

    // 3. qkv = dw3x3(hidden) -> buf2 [M,768] bf16
    dw_k<768, false><<<dim3(256, 48, 2), 256>>>(buf1, w_dw1, buf2);

    // 4. va = v * LN2(patchconv(q,k)) -> buf1 [M,256] bf16
    attn_k<<<dim3(1024, 1, 2), 256, 65792>>>(buf2, n2w, n2b, buf1);

    // 5. x1 = x + scale1 * (va @ w_p1^T) -> buf2 as fp32 NHWC [M,128]
    gemm_tc<256, 2><<<dim3(1024, 1), 256>>>(buf1, wb + 98304, nullptr, x, sc1, x1f, 128);

    // 6. LN3: x1 -> hn bf16 NHWC
    ln3_k<<<16384, 256>>>(x1f, n3w, n3b, hn);

    // 7. g = hn @ w_h2^T + b_h2 -> buf1 [M,256] bf16
    gemm_tc<128, 1><<<dim3(1024, 2), 256>>>(hn, wb + 131072, b_h2, nullptr, nullptr, buf1, 256);

    // 8. mgate = dw(g)[0:128] * dw(g)[128:256] -> hn [M,128] bf16
    dw_k<256, true><<<dim3(256, 8, 2), 256>>>(buf1, w_dw2, hn);

    // 9. out = x1 + scale2 * (mgate @ w_p2^T) -> d_out NCHW fp32
    gemm_tc<128, 3><<<dim3(1024, 1), 256>>>(hn, wb + 163840, nullptr, x1f, sc2, out, 128);
}